// round 10
// baseline (speedup 1.0000x reference)
#include <cuda_runtime.h>
#include <cuda_bf16.h>
#include <math.h>
#include <stdint.h>

// ---------------------------------------------------------------------------
// Problem constants: B=2, S=2048, E=1024, H=16, D=64
// ---------------------------------------------------------------------------
#define BATCH 2
#define SEQ   2048
#define EMB   1024
#define HEADS 16
#define HDIM  64
#define ROWS  (BATCH * SEQ)        // 4096
#define QKV_N (3 * EMB)            // 3072

// Scratch (allocation-free rule: __device__ globals)
__device__ float    g_qkv[ROWS * QKV_N];                    // 48 MB
__device__ float    g_attn[ROWS * EMB];                     // 16 MB
// Pre-split K/V in attention-smem word layout (bf16 hi/lo packed pairs)
__device__ uint32_t g_kh[BATCH * HEADS * SEQ * 32];         // 8 MB
__device__ uint32_t g_kl[BATCH * HEADS * SEQ * 32];         // 8 MB
__device__ uint32_t g_vh[BATCH * HEADS * (SEQ / 2) * 64];   // 8 MB
__device__ uint32_t g_vl[BATCH * HEADS * (SEQ / 2) * 64];   // 8 MB

// ---------------------------------------------------------------------------
// helpers
// ---------------------------------------------------------------------------
__device__ __forceinline__ uint32_t f32_to_tf32(float x) {
    uint32_t r;
    asm("cvt.rna.tf32.f32 %0, %1;" : "=r"(r) : "f"(x));
    return r;
}

__device__ __forceinline__ void mma_tf32_16x8x8(
    float& c0, float& c1, float& c2, float& c3,
    uint32_t a0, uint32_t a1, uint32_t a2, uint32_t a3,
    uint32_t b0, uint32_t b1)
{
    asm volatile(
        "mma.sync.aligned.m16n8k8.row.col.f32.tf32.tf32.f32 "
        "{%0,%1,%2,%3}, {%4,%5,%6,%7}, {%8,%9}, {%0,%1,%2,%3};"
        : "+f"(c0), "+f"(c1), "+f"(c2), "+f"(c3)
        : "r"(a0), "r"(a1), "r"(a2), "r"(a3), "r"(b0), "r"(b1));
}

__device__ __forceinline__ void mma_bf16_16x8x16(
    float& c0, float& c1, float& c2, float& c3,
    uint32_t a0, uint32_t a1, uint32_t a2, uint32_t a3,
    uint32_t b0, uint32_t b1)
{
    asm volatile(
        "mma.sync.aligned.m16n8k16.row.col.f32.bf16.bf16.f32 "
        "{%0,%1,%2,%3}, {%4,%5,%6,%7}, {%8,%9}, {%0,%1,%2,%3};"
        : "+f"(c0), "+f"(c1), "+f"(c2), "+f"(c3)
        : "r"(a0), "r"(a1), "r"(a2), "r"(a3), "r"(b0), "r"(b1));
}

__device__ __forceinline__ uint32_t pack_bf16(float a, float b) {
    __nv_bfloat162 p = __floats2bfloat162_rn(a, b);
    return *reinterpret_cast<uint32_t*>(&p);
}

__device__ __forceinline__ void split_bf16(float x, float& h, float& l) {
    h = __bfloat162float(__float2bfloat16_rn(x));
    l = x - h;
}

// ---------------------------------------------------------------------------
// tf32 tensor-core GEMM with fused bias. R6 base, but A stored in
// FRAGMENT-PERMUTED smem layout: Aperm[wm][kk][ma][lane] as uint4
// (a0,a1,a2,a3), block stride 33 uint4 -> frag load = 1 LDS.128,
// conflict-free; read broadcast across the 4 warp_n warps.
// B tile unchanged (stride 136, conflict-free b-frag reads).
// ---------------------------------------------------------------------------
template<int N, int K>
__device__ __forceinline__ void gemm_tf32(
    const float* __restrict__ A, const float* __restrict__ Bw,
    const float* __restrict__ bias, float* __restrict__ C)
{
    constexpr int BM = 128, BN = 128, BK = 32;
    constexpr int BS = BN + 8;     // 136

    __shared__ uint4    Aperm4[32 * 33];   // 32 blocks x 33 uint4 = 16896 B
    __shared__ uint32_t Bs[BK * BS];       // 17408 B

    uint32_t* Aw = reinterpret_cast<uint32_t*>(Aperm4);

    const int tid    = threadIdx.x;
    const int lane   = tid & 31;
    const int wid    = tid >> 5;
    const int warp_m = wid >> 2;
    const int warp_n = wid & 3;
    const int g      = lane >> 2;
    const int t      = lane & 3;

    const int cRow = blockIdx.y * BM;
    const int cCol = blockIdx.x * BN;

    float acc[4][4][4];
    #pragma unroll
    for (int i = 0; i < 4; i++)
        #pragma unroll
        for (int j = 0; j < 4; j++)
            #pragma unroll
            for (int r = 0; r < 4; r++) acc[i][j][r] = 0.f;

    for (int k0 = 0; k0 < K; k0 += BK) {
        // ---- A fill -> permuted layout.
        // word(m,c) = blk*132 + (m&7)*16 + 4*(c&3) + ((m>>3)&1) + 2*((c>>2)&1)
        // blk = ((m>>6)*4 + (c>>3))*4 + ((m>>4)&3)
        #pragma unroll
        for (int i = 0; i < 4; i++) {
            int idx = i * 256 + tid;
            int m   = idx >> 3;            // 0..127
            int c4  = (idx & 7) * 4;       // 0..28 (aligned 4)
            float4 v = *reinterpret_cast<const float4*>(
                A + (long)(cRow + m) * K + k0 + c4);
            int blk  = ((m >> 6) * 4 + (c4 >> 3)) * 4 + ((m >> 4) & 3);
            int base = blk * 132 + (m & 7) * 16 + ((m >> 3) & 1) + 2 * ((c4 >> 2) & 1);
            Aw[base +  0] = f32_to_tf32(v.x);
            Aw[base +  4] = f32_to_tf32(v.y);
            Aw[base +  8] = f32_to_tf32(v.z);
            Aw[base + 12] = f32_to_tf32(v.w);
        }
        // ---- B fill (unchanged from R6) ----
        #pragma unroll
        for (int i = 0; i < 4; i++) {
            int idx = i * 256 + tid;
            int kr  = idx >> 5;
            int nc  = (idx & 31) * 4;
            float4 v = *reinterpret_cast<const float4*>(
                Bw + (long)(k0 + kr) * N + cCol + nc);
            Bs[kr * BS + nc + 0] = f32_to_tf32(v.x);
            Bs[kr * BS + nc + 1] = f32_to_tf32(v.y);
            Bs[kr * BS + nc + 2] = f32_to_tf32(v.z);
            Bs[kr * BS + nc + 3] = f32_to_tf32(v.w);
        }
        __syncthreads();

        #pragma unroll
        for (int kk = 0; kk < 4; kk++) {
            const int k8 = kk * 8;
            uint4 a4[4];
            #pragma unroll
            for (int ma = 0; ma < 4; ma++)
                a4[ma] = Aperm4[((warp_m * 4 + kk) * 4 + ma) * 33 + lane];
            uint32_t b[4][2];
            #pragma unroll
            for (int na = 0; na < 4; na++) {
                int col = warp_n * 32 + na * 8 + g;
                b[na][0] = Bs[(k8 + t) * BS + col];
                b[na][1] = Bs[(k8 + t + 4) * BS + col];
            }
            #pragma unroll
            for (int ma = 0; ma < 4; ma++)
                #pragma unroll
                for (int na = 0; na < 4; na++)
                    mma_tf32_16x8x8(acc[ma][na][0], acc[ma][na][1],
                                    acc[ma][na][2], acc[ma][na][3],
                                    a4[ma].x, a4[ma].y, a4[ma].z, a4[ma].w,
                                    b[na][0], b[na][1]);
        }
        __syncthreads();
    }

    #pragma unroll
    for (int ma = 0; ma < 4; ma++) {
        #pragma unroll
        for (int na = 0; na < 4; na++) {
            int row = cRow + warp_m * 64 + ma * 16 + g;
            int col = cCol + warp_n * 32 + na * 8 + 2 * t;
            float2 bv = *reinterpret_cast<const float2*>(bias + col);
            float2 v0, v1;
            v0.x = acc[ma][na][0] + bv.x;
            v0.y = acc[ma][na][1] + bv.y;
            v1.x = acc[ma][na][2] + bv.x;
            v1.y = acc[ma][na][3] + bv.y;
            *reinterpret_cast<float2*>(C + (long)row * N + col)       = v0;
            *reinterpret_cast<float2*>(C + (long)(row + 8) * N + col) = v1;
        }
    }
}

__global__ __launch_bounds__(256) void qkv_tf32_kernel(
    const float* __restrict__ A, const float* __restrict__ Bw,
    const float* __restrict__ bias)
{
    gemm_tf32<QKV_N, EMB>(A, Bw, bias, g_qkv);
}

__global__ __launch_bounds__(256) void proj_tf32_kernel(
    const float* __restrict__ Bw, const float* __restrict__ bias,
    float* __restrict__ C)
{
    gemm_tf32<EMB, EMB>(g_attn, Bw, bias, C);
}

// ---------------------------------------------------------------------------
// Presplit kernels: split K/V into bf16 hi/lo packed words ONCE, in the
// exact smem word layout the attention kernel uses. Removes the ~16x
// redundant split/pack ALU from the attention hot loop.
// ---------------------------------------------------------------------------
__global__ __launch_bounds__(256) void presplit_k_kernel()
{
    const int r   = blockIdx.x;                // b*SEQ + s
    const int b   = r >> 11, s = r & (SEQ - 1);
    const int dg  = threadIdx.x * 4;           // 0..1020
    const int h   = dg >> 6, d = dg & 63;
    float4 v = *reinterpret_cast<const float4*>(g_qkv + (long)r * QKV_N + EMB + dg);
    float h0, l0, h1, l1, h2, l2, h3, l3;
    split_bf16(v.x, h0, l0); split_bf16(v.y, h1, l1);
    split_bf16(v.z, h2, l2); split_bf16(v.w, h3, l3);
    long o = ((long)(b * HEADS + h) * SEQ + s) * 32 + (d >> 1);
    *reinterpret_cast<uint2*>(g_kh + o) = make_uint2(pack_bf16(h0, h1), pack_bf16(h2, h3));
    *reinterpret_cast<uint2*>(g_kl + o) = make_uint2(pack_bf16(l0, l1), pack_bf16(l2, l3));
}

__global__ __launch_bounds__(256) void presplit_v_kernel()
{
    const int p   = blockIdx.x;                // b*(SEQ/2) + sp
    const int b   = p >> 10, sp = p & (SEQ / 2 - 1);
    const int dg  = threadIdx.x * 4;
    const int h   = dg >> 6, d = dg & 63;
    const long rbase = (long)(b * SEQ + 2 * sp) * QKV_N + 2 * EMB + dg;
    float4 v0 = *reinterpret_cast<const float4*>(g_qkv + rbase);
    float4 v1 = *reinterpret_cast<const float4*>(g_qkv + rbase + QKV_N);
    float ha, la, hb, lb;
    uint4 oh, ol;
    split_bf16(v0.x, ha, la); split_bf16(v1.x, hb, lb);
    oh.x = pack_bf16(ha, hb); ol.x = pack_bf16(la, lb);
    split_bf16(v0.y, ha, la); split_bf16(v1.y, hb, lb);
    oh.y = pack_bf16(ha, hb); ol.y = pack_bf16(la, lb);
    split_bf16(v0.z, ha, la); split_bf16(v1.z, hb, lb);
    oh.z = pack_bf16(ha, hb); ol.z = pack_bf16(la, lb);
    split_bf16(v0.w, ha, la); split_bf16(v1.w, hb, lb);
    oh.w = pack_bf16(ha, hb); ol.w = pack_bf16(la, lb);
    long o = ((long)(b * HEADS + h) * (SEQ / 2) + sp) * 64 + d;
    *reinterpret_cast<uint4*>(g_vh + o) = oh;
    *reinterpret_cast<uint4*>(g_vl + o) = ol;
}

// ---------------------------------------------------------------------------
// Flash attention, bf16 split tensor cores (m16n8k16), register-prefetch
// fills from PRE-SPLIT gmem (pure LDG.128 -> STS.128, no conversion ALU).
// Math identical to R6/R9.
// ---------------------------------------------------------------------------
#define KW_STRIDE 36   // words per key row (32 dim-pairs + 4 pad)
#define VW_STRIDE 72   // words per key-pair row (64 dims + 8 pad)

__global__ __launch_bounds__(256) void flash_attn_mma_kernel()
{
    const int qt   = (int)gridDim.x - 1 - (int)blockIdx.x;  // heavy blocks first
    const int h    = blockIdx.y;
    const int b    = blockIdx.z;
    const int tid  = threadIdx.x;
    const int lane = tid & 31;
    const int w    = tid >> 5;
    const int g    = lane >> 2;   // 0..7
    const int t    = lane & 3;    // 0..3

    const int qbase = qt * 128;
    const int row0  = qbase + w * 16 + g;
    const int hoff  = h * HDIM;

    __shared__ uint32_t Kh[64 * KW_STRIDE];
    __shared__ uint32_t Kl[64 * KW_STRIDE];
    __shared__ uint32_t Vph[32 * VW_STRIDE];
    __shared__ uint32_t Vpl[32 * VW_STRIDE];

    uint32_t qh[4][4], ql[4][4];
    {
        const long r0 = (long)(b * SEQ + row0) * QKV_N + hoff;
        const long r1 = r0 + 8L * QKV_N;
        #pragma unroll
        for (int kk = 0; kk < 4; kk++) {
            int d0 = kk * 16 + 2 * t;
            int d1 = d0 + 8;
            float hx, lx, hy, ly;
            split_bf16(g_qkv[r0 + d0] * 0.125f, hx, lx);
            split_bf16(g_qkv[r0 + d0 + 1] * 0.125f, hy, ly);
            qh[kk][0] = pack_bf16(hx, hy);  ql[kk][0] = pack_bf16(lx, ly);
            split_bf16(g_qkv[r1 + d0] * 0.125f, hx, lx);
            split_bf16(g_qkv[r1 + d0 + 1] * 0.125f, hy, ly);
            qh[kk][1] = pack_bf16(hx, hy);  ql[kk][1] = pack_bf16(lx, ly);
            split_bf16(g_qkv[r0 + d1] * 0.125f, hx, lx);
            split_bf16(g_qkv[r0 + d1 + 1] * 0.125f, hy, ly);
            qh[kk][2] = pack_bf16(hx, hy);  ql[kk][2] = pack_bf16(lx, ly);
            split_bf16(g_qkv[r1 + d1] * 0.125f, hx, lx);
            split_bf16(g_qkv[r1 + d1 + 1] * 0.125f, hy, ly);
            qh[kk][3] = pack_bf16(hx, hy);  ql[kk][3] = pack_bf16(lx, ly);
        }
    }

    float o[8][4];
    #pragma unroll
    for (int na = 0; na < 8; na++)
        #pragma unroll
        for (int e = 0; e < 4; e++) o[na][e] = 0.f;
    float m0 = -INFINITY, m1 = -INFINITY, l0 = 0.f, l1 = 0.f;

    // prefetch registers (8 uint4 = 32 regs)
    uint4 pkh[2], pkl[2], pvh[2], pvl[2];

    const long khbase = (long)(b * HEADS + h) * SEQ * 32;
    const long vbase0 = (long)(b * HEADS + h) * (SEQ / 2) * 64;

    auto ldg_tile = [&](int kt) {
        const long kb = khbase + (long)kt * 64 * 32;
        #pragma unroll
        for (int i = 0; i < 2; i++) {
            int idx = i * 256 + tid;
            int j   = idx >> 3;            // key row 0..63
            int wq  = idx & 7;             // uint4 within row
            pkh[i] = *reinterpret_cast<const uint4*>(g_kh + kb + j * 32 + wq * 4);
            pkl[i] = *reinterpret_cast<const uint4*>(g_kl + kb + j * 32 + wq * 4);
        }
        const long vb = vbase0 + (long)kt * 32 * 64;
        #pragma unroll
        for (int i = 0; i < 2; i++) {
            int idx = i * 256 + tid;
            int jp  = idx >> 4;            // pair row 0..31
            int wq  = idx & 15;
            pvh[i] = *reinterpret_cast<const uint4*>(g_vh + vb + jp * 64 + wq * 4);
            pvl[i] = *reinterpret_cast<const uint4*>(g_vl + vb + jp * 64 + wq * 4);
        }
    };

    const int ntiles = 2 * qt + 2;
    ldg_tile(0);

    for (int kt = 0; kt < ntiles; kt++) {
        // ---- STS from prefetched registers (no conversion) ----
        #pragma unroll
        for (int i = 0; i < 2; i++) {
            int idx = i * 256 + tid;
            int j   = idx >> 3;
            int wq  = idx & 7;
            *reinterpret_cast<uint4*>(&Kh[j * KW_STRIDE + wq * 4]) = pkh[i];
            *reinterpret_cast<uint4*>(&Kl[j * KW_STRIDE + wq * 4]) = pkl[i];
        }
        #pragma unroll
        for (int i = 0; i < 2; i++) {
            int idx = i * 256 + tid;
            int jp  = idx >> 4;
            int wq  = idx & 15;
            *reinterpret_cast<uint4*>(&Vph[jp * VW_STRIDE + wq * 4]) = pvh[i];
            *reinterpret_cast<uint4*>(&Vpl[jp * VW_STRIDE + wq * 4]) = pvl[i];
        }
        __syncthreads();

        // ---- prefetch next tile (overlaps mma phase) ----
        if (kt + 1 < ntiles) ldg_tile(kt + 1);

        // ---- scores S = Q K^T (3-term bf16 split) ----
        float s[8][4];
        #pragma unroll
        for (int na = 0; na < 8; na++)
            #pragma unroll
            for (int e = 0; e < 4; e++) s[na][e] = 0.f;

        #pragma unroll
        for (int kk = 0; kk < 4; kk++) {
            const int w0 = kk * 8 + t;
            #pragma unroll
            for (int na = 0; na < 8; na++) {
                int key = na * 8 + g;
                uint32_t bh0 = Kh[key * KW_STRIDE + w0];
                uint32_t bh1 = Kh[key * KW_STRIDE + w0 + 4];
                uint32_t bl0 = Kl[key * KW_STRIDE + w0];
                uint32_t bl1 = Kl[key * KW_STRIDE + w0 + 4];
                mma_bf16_16x8x16(s[na][0], s[na][1], s[na][2], s[na][3],
                                 qh[kk][0], qh[kk][1], qh[kk][2], qh[kk][3], bh0, bh1);
                mma_bf16_16x8x16(s[na][0], s[na][1], s[na][2], s[na][3],
                                 ql[kk][0], ql[kk][1], ql[kk][2], ql[kk][3], bh0, bh1);
                mma_bf16_16x8x16(s[na][0], s[na][1], s[na][2], s[na][3],
                                 qh[kk][0], qh[kk][1], qh[kk][2], qh[kk][3], bl0, bl1);
            }
        }

        // ---- causal mask (diagonal tiles only) ----
        if (kt >= 2 * qt) {
            const int colbase = kt * 64 + 2 * t;
            #pragma unroll
            for (int na = 0; na < 8; na++) {
                int c = colbase + 8 * na;
                if (c     > row0)     s[na][0] = -INFINITY;
                if (c + 1 > row0)     s[na][1] = -INFINITY;
                if (c     > row0 + 8) s[na][2] = -INFINITY;
                if (c + 1 > row0 + 8) s[na][3] = -INFINITY;
            }
        }

        // ---- online softmax ----
        float tm0 = -INFINITY, tm1 = -INFINITY;
        #pragma unroll
        for (int na = 0; na < 8; na++) {
            tm0 = fmaxf(tm0, fmaxf(s[na][0], s[na][1]));
            tm1 = fmaxf(tm1, fmaxf(s[na][2], s[na][3]));
        }
        tm0 = fmaxf(tm0, __shfl_xor_sync(0xffffffffu, tm0, 1));
        tm0 = fmaxf(tm0, __shfl_xor_sync(0xffffffffu, tm0, 2));
        tm1 = fmaxf(tm1, __shfl_xor_sync(0xffffffffu, tm1, 1));
        tm1 = fmaxf(tm1, __shfl_xor_sync(0xffffffffu, tm1, 2));

        float mn0 = fmaxf(m0, tm0), mn1 = fmaxf(m1, tm1);
        float a0 = __expf(m0 - mn0), a1 = __expf(m1 - mn1);
        l0 *= a0; l1 *= a1;
        #pragma unroll
        for (int na = 0; na < 8; na++) {
            o[na][0] *= a0; o[na][1] *= a0;
            o[na][2] *= a1; o[na][3] *= a1;
        }

        float rs0 = 0.f, rs1 = 0.f;
        #pragma unroll
        for (int na = 0; na < 8; na++) {
            s[na][0] = __expf(s[na][0] - mn0);
            s[na][1] = __expf(s[na][1] - mn0);
            s[na][2] = __expf(s[na][2] - mn1);
            s[na][3] = __expf(s[na][3] - mn1);
            rs0 += s[na][0] + s[na][1];
            rs1 += s[na][2] + s[na][3];
        }
        rs0 += __shfl_xor_sync(0xffffffffu, rs0, 1);
        rs0 += __shfl_xor_sync(0xffffffffu, rs0, 2);
        rs1 += __shfl_xor_sync(0xffffffffu, rs1, 1);
        rs1 += __shfl_xor_sync(0xffffffffu, rs1, 2);
        l0 += rs0; l1 += rs1;
        m0 = mn0; m1 = mn1;

        // ---- O += P V (S C-frag IS P A-frag; 3-term split) ----
        #pragma unroll
        for (int kk = 0; kk < 4; kk++) {
            const int n0 = 2 * kk;
            float h0, lo0, h1, lo1;
            uint32_t ph[4], pl[4];
            split_bf16(s[n0][0], h0, lo0);  split_bf16(s[n0][1], h1, lo1);
            ph[0] = pack_bf16(h0, h1);      pl[0] = pack_bf16(lo0, lo1);
            split_bf16(s[n0][2], h0, lo0);  split_bf16(s[n0][3], h1, lo1);
            ph[1] = pack_bf16(h0, h1);      pl[1] = pack_bf16(lo0, lo1);
            split_bf16(s[n0 + 1][0], h0, lo0);  split_bf16(s[n0 + 1][1], h1, lo1);
            ph[2] = pack_bf16(h0, h1);      pl[2] = pack_bf16(lo0, lo1);
            split_bf16(s[n0 + 1][2], h0, lo0);  split_bf16(s[n0 + 1][3], h1, lo1);
            ph[3] = pack_bf16(h0, h1);      pl[3] = pack_bf16(lo0, lo1);

            const int r0w = (8 * kk + t) * VW_STRIDE;
            const int r1w = (8 * kk + t + 4) * VW_STRIDE;
            #pragma unroll
            for (int na = 0; na < 8; na++) {
                int col = na * 8 + g;
                uint32_t bh0 = Vph[r0w + col], bh1 = Vph[r1w + col];
                uint32_t bl0 = Vpl[r0w + col], bl1 = Vpl[r1w + col];
                mma_bf16_16x8x16(o[na][0], o[na][1], o[na][2], o[na][3],
                                 ph[0], ph[1], ph[2], ph[3], bh0, bh1);
                mma_bf16_16x8x16(o[na][0], o[na][1], o[na][2], o[na][3],
                                 pl[0], pl[1], pl[2], pl[3], bh0, bh1);
                mma_bf16_16x8x16(o[na][0], o[na][1], o[na][2], o[na][3],
                                 ph[0], ph[1], ph[2], ph[3], bl0, bl1);
            }
        }
        __syncthreads();
    }

    const float inv0 = 1.f / l0, inv1 = 1.f / l1;
    const long ob0 = (long)(b * SEQ + row0) * EMB + hoff;
    const long ob1 = ob0 + 8L * EMB;
    #pragma unroll
    for (int na = 0; na < 8; na++) {
        int col = na * 8 + 2 * t;
        float2 w0 = make_float2(o[na][0] * inv0, o[na][1] * inv0);
        float2 w1 = make_float2(o[na][2] * inv1, o[na][3] * inv1);
        *reinterpret_cast<float2*>(g_attn + ob0 + col) = w0;
        *reinterpret_cast<float2*>(g_attn + ob1 + col) = w1;
    }
}

// ---------------------------------------------------------------------------
// Launch: five kernel launches, nothing else.
// ---------------------------------------------------------------------------
extern "C" void kernel_launch(void* const* d_in, const int* in_sizes, int n_in,
                              void* d_out, int out_size)
{
    const float* hidden = (const float*)d_in[0];
    const float* w_attn = (const float*)d_in[1];
    const float* b_attn = (const float*)d_in[2];
    const float* w_proj = (const float*)d_in[3];
    const float* b_proj = (const float*)d_in[4];
    float* out = (float*)d_out;

    // 1) QKV projection (tf32 TC, A-perm frag layout) -> g_qkv
    qkv_tf32_kernel<<<dim3(QKV_N / 128, ROWS / 128), 256>>>(hidden, w_attn, b_attn);

    // 2) Presplit K/V into bf16 hi/lo packed word layout
    presplit_k_kernel<<<ROWS, 256>>>();
    presplit_v_kernel<<<ROWS / 2, 256>>>();

    // 3) Causal MHA, bf16-split MMA flash attention -> g_attn
    flash_attn_mma_kernel<<<dim3(SEQ / 128, HEADS, BATCH), 256>>>();

    // 4) Output projection (tf32 TC, A-perm frag layout) -> out
    proj_tf32_kernel<<<dim3(EMB / 128, ROWS / 128), 256>>>(w_proj, b_proj, out);
}

// round 11
// speedup vs baseline: 1.1591x; 1.1591x over previous
#include <cuda_runtime.h>
#include <cuda_bf16.h>
#include <math.h>
#include <stdint.h>

// ---------------------------------------------------------------------------
// Problem constants: B=2, S=2048, E=1024, H=16, D=64
// ---------------------------------------------------------------------------
#define BATCH 2
#define SEQ   2048
#define EMB   1024
#define HEADS 16
#define HDIM  64
#define ROWS  (BATCH * SEQ)        // 4096
#define QKV_N (3 * EMB)            // 3072

// Scratch (allocation-free rule: __device__ globals)
__device__ float    g_qkv[ROWS * QKV_N];                    // 48 MB
__device__ float    g_attn[ROWS * EMB];                     // 16 MB
// Pre-split K/V in attention-smem word layout (bf16 hi/lo packed pairs)
__device__ uint32_t g_kh[BATCH * HEADS * SEQ * 32];         // 8 MB
__device__ uint32_t g_kl[BATCH * HEADS * SEQ * 32];         // 8 MB
__device__ uint32_t g_vh[BATCH * HEADS * (SEQ / 2) * 64];   // 8 MB
__device__ uint32_t g_vl[BATCH * HEADS * (SEQ / 2) * 64];   // 8 MB

// ---------------------------------------------------------------------------
// helpers
// ---------------------------------------------------------------------------
__device__ __forceinline__ uint32_t f32_to_tf32(float x) {
    uint32_t r;
    asm("cvt.rna.tf32.f32 %0, %1;" : "=r"(r) : "f"(x));
    return r;
}

__device__ __forceinline__ void mma_tf32_16x8x8(
    float& c0, float& c1, float& c2, float& c3,
    uint32_t a0, uint32_t a1, uint32_t a2, uint32_t a3,
    uint32_t b0, uint32_t b1)
{
    asm volatile(
        "mma.sync.aligned.m16n8k8.row.col.f32.tf32.tf32.f32 "
        "{%0,%1,%2,%3}, {%4,%5,%6,%7}, {%8,%9}, {%0,%1,%2,%3};"
        : "+f"(c0), "+f"(c1), "+f"(c2), "+f"(c3)
        : "r"(a0), "r"(a1), "r"(a2), "r"(a3), "r"(b0), "r"(b1));
}

__device__ __forceinline__ void mma_bf16_16x8x16(
    float& c0, float& c1, float& c2, float& c3,
    uint32_t a0, uint32_t a1, uint32_t a2, uint32_t a3,
    uint32_t b0, uint32_t b1)
{
    asm volatile(
        "mma.sync.aligned.m16n8k16.row.col.f32.bf16.bf16.f32 "
        "{%0,%1,%2,%3}, {%4,%5,%6,%7}, {%8,%9}, {%0,%1,%2,%3};"
        : "+f"(c0), "+f"(c1), "+f"(c2), "+f"(c3)
        : "r"(a0), "r"(a1), "r"(a2), "r"(a3), "r"(b0), "r"(b1));
}

__device__ __forceinline__ uint32_t pack_bf16(float a, float b) {
    __nv_bfloat162 p = __floats2bfloat162_rn(a, b);
    return *reinterpret_cast<uint32_t*>(&p);
}

__device__ __forceinline__ void split_bf16(float x, float& h, float& l) {
    h = __bfloat162float(__float2bfloat16_rn(x));
    l = x - h;
}

// ---------------------------------------------------------------------------
// tf32 tensor-core GEMM with fused bias — R6/R9 version (fill-time cvt,
// BK=32, A stride 36 / B stride 136). Measured 218us (QKV) / ~70us (proj).
// ---------------------------------------------------------------------------
template<int N, int K>
__device__ __forceinline__ void gemm_tf32(
    const float* __restrict__ A, const float* __restrict__ Bw,
    const float* __restrict__ bias, float* __restrict__ C)
{
    constexpr int BM = 128, BN = 128, BK = 32;
    constexpr int AS = BK + 4;
    constexpr int BS = BN + 8;

    __shared__ uint32_t As[BM * AS];
    __shared__ uint32_t Bs[BK * BS];

    const int tid    = threadIdx.x;
    const int lane   = tid & 31;
    const int wid    = tid >> 5;
    const int warp_m = wid >> 2;
    const int warp_n = wid & 3;
    const int g      = lane >> 2;
    const int t      = lane & 3;

    const int cRow = blockIdx.y * BM;
    const int cCol = blockIdx.x * BN;

    float acc[4][4][4];
    #pragma unroll
    for (int i = 0; i < 4; i++)
        #pragma unroll
        for (int j = 0; j < 4; j++)
            #pragma unroll
            for (int r = 0; r < 4; r++) acc[i][j][r] = 0.f;

    for (int k0 = 0; k0 < K; k0 += BK) {
        #pragma unroll
        for (int i = 0; i < 4; i++) {
            int idx = i * 256 + tid;
            int m   = idx >> 3;
            int c4  = (idx & 7) * 4;
            float4 v = *reinterpret_cast<const float4*>(
                A + (long)(cRow + m) * K + k0 + c4);
            As[m * AS + c4 + 0] = f32_to_tf32(v.x);
            As[m * AS + c4 + 1] = f32_to_tf32(v.y);
            As[m * AS + c4 + 2] = f32_to_tf32(v.z);
            As[m * AS + c4 + 3] = f32_to_tf32(v.w);
        }
        #pragma unroll
        for (int i = 0; i < 4; i++) {
            int idx = i * 256 + tid;
            int kr  = idx >> 5;
            int nc  = (idx & 31) * 4;
            float4 v = *reinterpret_cast<const float4*>(
                Bw + (long)(k0 + kr) * N + cCol + nc);
            Bs[kr * BS + nc + 0] = f32_to_tf32(v.x);
            Bs[kr * BS + nc + 1] = f32_to_tf32(v.y);
            Bs[kr * BS + nc + 2] = f32_to_tf32(v.z);
            Bs[kr * BS + nc + 3] = f32_to_tf32(v.w);
        }
        __syncthreads();

        #pragma unroll
        for (int kk = 0; kk < 4; kk++) {
            const int k8 = kk * 8;
            uint32_t a[4][4];
            #pragma unroll
            for (int ma = 0; ma < 4; ma++) {
                int row = warp_m * 64 + ma * 16;
                a[ma][0] = As[(row + g) * AS + k8 + t];
                a[ma][1] = As[(row + g + 8) * AS + k8 + t];
                a[ma][2] = As[(row + g) * AS + k8 + t + 4];
                a[ma][3] = As[(row + g + 8) * AS + k8 + t + 4];
            }
            uint32_t b[4][2];
            #pragma unroll
            for (int na = 0; na < 4; na++) {
                int col = warp_n * 32 + na * 8 + g;
                b[na][0] = Bs[(k8 + t) * BS + col];
                b[na][1] = Bs[(k8 + t + 4) * BS + col];
            }
            #pragma unroll
            for (int ma = 0; ma < 4; ma++)
                #pragma unroll
                for (int na = 0; na < 4; na++)
                    mma_tf32_16x8x8(acc[ma][na][0], acc[ma][na][1],
                                    acc[ma][na][2], acc[ma][na][3],
                                    a[ma][0], a[ma][1], a[ma][2], a[ma][3],
                                    b[na][0], b[na][1]);
        }
        __syncthreads();
    }

    #pragma unroll
    for (int ma = 0; ma < 4; ma++) {
        #pragma unroll
        for (int na = 0; na < 4; na++) {
            int row = cRow + warp_m * 64 + ma * 16 + g;
            int col = cCol + warp_n * 32 + na * 8 + 2 * t;
            float2 bv = *reinterpret_cast<const float2*>(bias + col);
            float2 v0, v1;
            v0.x = acc[ma][na][0] + bv.x;
            v0.y = acc[ma][na][1] + bv.y;
            v1.x = acc[ma][na][2] + bv.x;
            v1.y = acc[ma][na][3] + bv.y;
            *reinterpret_cast<float2*>(C + (long)row * N + col)       = v0;
            *reinterpret_cast<float2*>(C + (long)(row + 8) * N + col) = v1;
        }
    }
}

__global__ __launch_bounds__(256) void qkv_tf32_kernel(
    const float* __restrict__ A, const float* __restrict__ Bw,
    const float* __restrict__ bias)
{
    gemm_tf32<QKV_N, EMB>(A, Bw, bias, g_qkv);
}

__global__ __launch_bounds__(256) void proj_tf32_kernel(
    const float* __restrict__ Bw, const float* __restrict__ bias,
    float* __restrict__ C)
{
    gemm_tf32<EMB, EMB>(g_attn, Bw, bias, C);
}

// ---------------------------------------------------------------------------
// Presplit kernels (R10, measured good): split K/V into bf16 hi/lo packed
// words once, in the exact smem word layout the attention kernel uses.
// ---------------------------------------------------------------------------
__global__ __launch_bounds__(256) void presplit_k_kernel()
{
    const int r   = blockIdx.x;                // b*SEQ + s
    const int b   = r >> 11, s = r & (SEQ - 1);
    const int dg  = threadIdx.x * 4;           // 0..1020
    const int h   = dg >> 6, d = dg & 63;
    float4 v = *reinterpret_cast<const float4*>(g_qkv + (long)r * QKV_N + EMB + dg);
    float h0, l0, h1, l1, h2, l2, h3, l3;
    split_bf16(v.x, h0, l0); split_bf16(v.y, h1, l1);
    split_bf16(v.z, h2, l2); split_bf16(v.w, h3, l3);
    long o = ((long)(b * HEADS + h) * SEQ + s) * 32 + (d >> 1);
    *reinterpret_cast<uint2*>(g_kh + o) = make_uint2(pack_bf16(h0, h1), pack_bf16(h2, h3));
    *reinterpret_cast<uint2*>(g_kl + o) = make_uint2(pack_bf16(l0, l1), pack_bf16(l2, l3));
}

__global__ __launch_bounds__(256) void presplit_v_kernel()
{
    const int p   = blockIdx.x;                // b*(SEQ/2) + sp
    const int b   = p >> 10, sp = p & (SEQ / 2 - 1);
    const int dg  = threadIdx.x * 4;
    const int h   = dg >> 6, d = dg & 63;
    const long rbase = (long)(b * SEQ + 2 * sp) * QKV_N + 2 * EMB + dg;
    float4 v0 = *reinterpret_cast<const float4*>(g_qkv + rbase);
    float4 v1 = *reinterpret_cast<const float4*>(g_qkv + rbase + QKV_N);
    float ha, la, hb, lb;
    uint4 oh, ol;
    split_bf16(v0.x, ha, la); split_bf16(v1.x, hb, lb);
    oh.x = pack_bf16(ha, hb); ol.x = pack_bf16(la, lb);
    split_bf16(v0.y, ha, la); split_bf16(v1.y, hb, lb);
    oh.y = pack_bf16(ha, hb); ol.y = pack_bf16(la, lb);
    split_bf16(v0.z, ha, la); split_bf16(v1.z, hb, lb);
    oh.z = pack_bf16(ha, hb); ol.z = pack_bf16(la, lb);
    split_bf16(v0.w, ha, la); split_bf16(v1.w, hb, lb);
    oh.w = pack_bf16(ha, hb); ol.w = pack_bf16(la, lb);
    long o = ((long)(b * HEADS + h) * (SEQ / 2) + sp) * 64 + d;
    *reinterpret_cast<uint4*>(g_vh + o) = oh;
    *reinterpret_cast<uint4*>(g_vl + o) = ol;
}

// ---------------------------------------------------------------------------
// Flash attention (R10, measured 259us): bf16 split m16n8k16, register-
// prefetch fills from pre-split gmem (pure LDG.128 -> STS.128).
// ---------------------------------------------------------------------------
#define KW_STRIDE 36   // words per key row (32 dim-pairs + 4 pad)
#define VW_STRIDE 72   // words per key-pair row (64 dims + 8 pad)

__global__ __launch_bounds__(256) void flash_attn_mma_kernel()
{
    const int qt   = (int)gridDim.x - 1 - (int)blockIdx.x;  // heavy blocks first
    const int h    = blockIdx.y;
    const int b    = blockIdx.z;
    const int tid  = threadIdx.x;
    const int lane = tid & 31;
    const int w    = tid >> 5;
    const int g    = lane >> 2;   // 0..7
    const int t    = lane & 3;    // 0..3

    const int qbase = qt * 128;
    const int row0  = qbase + w * 16 + g;
    const int hoff  = h * HDIM;

    __shared__ uint32_t Kh[64 * KW_STRIDE];
    __shared__ uint32_t Kl[64 * KW_STRIDE];
    __shared__ uint32_t Vph[32 * VW_STRIDE];
    __shared__ uint32_t Vpl[32 * VW_STRIDE];

    uint32_t qh[4][4], ql[4][4];
    {
        const long r0 = (long)(b * SEQ + row0) * QKV_N + hoff;
        const long r1 = r0 + 8L * QKV_N;
        #pragma unroll
        for (int kk = 0; kk < 4; kk++) {
            int d0 = kk * 16 + 2 * t;
            int d1 = d0 + 8;
            float hx, lx, hy, ly;
            split_bf16(g_qkv[r0 + d0] * 0.125f, hx, lx);
            split_bf16(g_qkv[r0 + d0 + 1] * 0.125f, hy, ly);
            qh[kk][0] = pack_bf16(hx, hy);  ql[kk][0] = pack_bf16(lx, ly);
            split_bf16(g_qkv[r1 + d0] * 0.125f, hx, lx);
            split_bf16(g_qkv[r1 + d0 + 1] * 0.125f, hy, ly);
            qh[kk][1] = pack_bf16(hx, hy);  ql[kk][1] = pack_bf16(lx, ly);
            split_bf16(g_qkv[r0 + d1] * 0.125f, hx, lx);
            split_bf16(g_qkv[r0 + d1 + 1] * 0.125f, hy, ly);
            qh[kk][2] = pack_bf16(hx, hy);  ql[kk][2] = pack_bf16(lx, ly);
            split_bf16(g_qkv[r1 + d1] * 0.125f, hx, lx);
            split_bf16(g_qkv[r1 + d1 + 1] * 0.125f, hy, ly);
            qh[kk][3] = pack_bf16(hx, hy);  ql[kk][3] = pack_bf16(lx, ly);
        }
    }

    float o[8][4];
    #pragma unroll
    for (int na = 0; na < 8; na++)
        #pragma unroll
        for (int e = 0; e < 4; e++) o[na][e] = 0.f;
    float m0 = -INFINITY, m1 = -INFINITY, l0 = 0.f, l1 = 0.f;

    // prefetch registers (8 uint4 = 32 regs)
    uint4 pkh[2], pkl[2], pvh[2], pvl[2];

    const long khbase = (long)(b * HEADS + h) * SEQ * 32;
    const long vbase0 = (long)(b * HEADS + h) * (SEQ / 2) * 64;

    auto ldg_tile = [&](int kt) {
        const long kb = khbase + (long)kt * 64 * 32;
        #pragma unroll
        for (int i = 0; i < 2; i++) {
            int idx = i * 256 + tid;
            int j   = idx >> 3;            // key row 0..63
            int wq  = idx & 7;             // uint4 within row
            pkh[i] = *reinterpret_cast<const uint4*>(g_kh + kb + j * 32 + wq * 4);
            pkl[i] = *reinterpret_cast<const uint4*>(g_kl + kb + j * 32 + wq * 4);
        }
        const long vb = vbase0 + (long)kt * 32 * 64;
        #pragma unroll
        for (int i = 0; i < 2; i++) {
            int idx = i * 256 + tid;
            int jp  = idx >> 4;            // pair row 0..31
            int wq  = idx & 15;
            pvh[i] = *reinterpret_cast<const uint4*>(g_vh + vb + jp * 64 + wq * 4);
            pvl[i] = *reinterpret_cast<const uint4*>(g_vl + vb + jp * 64 + wq * 4);
        }
    };

    const int ntiles = 2 * qt + 2;
    ldg_tile(0);

    for (int kt = 0; kt < ntiles; kt++) {
        // ---- STS from prefetched registers (no conversion) ----
        #pragma unroll
        for (int i = 0; i < 2; i++) {
            int idx = i * 256 + tid;
            int j   = idx >> 3;
            int wq  = idx & 7;
            *reinterpret_cast<uint4*>(&Kh[j * KW_STRIDE + wq * 4]) = pkh[i];
            *reinterpret_cast<uint4*>(&Kl[j * KW_STRIDE + wq * 4]) = pkl[i];
        }
        #pragma unroll
        for (int i = 0; i < 2; i++) {
            int idx = i * 256 + tid;
            int jp  = idx >> 4;
            int wq  = idx & 15;
            *reinterpret_cast<uint4*>(&Vph[jp * VW_STRIDE + wq * 4]) = pvh[i];
            *reinterpret_cast<uint4*>(&Vpl[jp * VW_STRIDE + wq * 4]) = pvl[i];
        }
        __syncthreads();

        // ---- prefetch next tile (overlaps mma phase) ----
        if (kt + 1 < ntiles) ldg_tile(kt + 1);

        // ---- scores S = Q K^T (3-term bf16 split) ----
        float s[8][4];
        #pragma unroll
        for (int na = 0; na < 8; na++)
            #pragma unroll
            for (int e = 0; e < 4; e++) s[na][e] = 0.f;

        #pragma unroll
        for (int kk = 0; kk < 4; kk++) {
            const int w0 = kk * 8 + t;
            #pragma unroll
            for (int na = 0; na < 8; na++) {
                int key = na * 8 + g;
                uint32_t bh0 = Kh[key * KW_STRIDE + w0];
                uint32_t bh1 = Kh[key * KW_STRIDE + w0 + 4];
                uint32_t bl0 = Kl[key * KW_STRIDE + w0];
                uint32_t bl1 = Kl[key * KW_STRIDE + w0 + 4];
                mma_bf16_16x8x16(s[na][0], s[na][1], s[na][2], s[na][3],
                                 qh[kk][0], qh[kk][1], qh[kk][2], qh[kk][3], bh0, bh1);
                mma_bf16_16x8x16(s[na][0], s[na][1], s[na][2], s[na][3],
                                 ql[kk][0], ql[kk][1], ql[kk][2], ql[kk][3], bh0, bh1);
                mma_bf16_16x8x16(s[na][0], s[na][1], s[na][2], s[na][3],
                                 qh[kk][0], qh[kk][1], qh[kk][2], qh[kk][3], bl0, bl1);
            }
        }

        // ---- causal mask (diagonal tiles only) ----
        if (kt >= 2 * qt) {
            const int colbase = kt * 64 + 2 * t;
            #pragma unroll
            for (int na = 0; na < 8; na++) {
                int c = colbase + 8 * na;
                if (c     > row0)     s[na][0] = -INFINITY;
                if (c + 1 > row0)     s[na][1] = -INFINITY;
                if (c     > row0 + 8) s[na][2] = -INFINITY;
                if (c + 1 > row0 + 8) s[na][3] = -INFINITY;
            }
        }

        // ---- online softmax ----
        float tm0 = -INFINITY, tm1 = -INFINITY;
        #pragma unroll
        for (int na = 0; na < 8; na++) {
            tm0 = fmaxf(tm0, fmaxf(s[na][0], s[na][1]));
            tm1 = fmaxf(tm1, fmaxf(s[na][2], s[na][3]));
        }
        tm0 = fmaxf(tm0, __shfl_xor_sync(0xffffffffu, tm0, 1));
        tm0 = fmaxf(tm0, __shfl_xor_sync(0xffffffffu, tm0, 2));
        tm1 = fmaxf(tm1, __shfl_xor_sync(0xffffffffu, tm1, 1));
        tm1 = fmaxf(tm1, __shfl_xor_sync(0xffffffffu, tm1, 2));

        float mn0 = fmaxf(m0, tm0), mn1 = fmaxf(m1, tm1);
        float a0 = __expf(m0 - mn0), a1 = __expf(m1 - mn1);
        l0 *= a0; l1 *= a1;
        #pragma unroll
        for (int na = 0; na < 8; na++) {
            o[na][0] *= a0; o[na][1] *= a0;
            o[na][2] *= a1; o[na][3] *= a1;
        }

        float rs0 = 0.f, rs1 = 0.f;
        #pragma unroll
        for (int na = 0; na < 8; na++) {
            s[na][0] = __expf(s[na][0] - mn0);
            s[na][1] = __expf(s[na][1] - mn0);
            s[na][2] = __expf(s[na][2] - mn1);
            s[na][3] = __expf(s[na][3] - mn1);
            rs0 += s[na][0] + s[na][1];
            rs1 += s[na][2] + s[na][3];
        }
        rs0 += __shfl_xor_sync(0xffffffffu, rs0, 1);
        rs0 += __shfl_xor_sync(0xffffffffu, rs0, 2);
        rs1 += __shfl_xor_sync(0xffffffffu, rs1, 1);
        rs1 += __shfl_xor_sync(0xffffffffu, rs1, 2);
        l0 += rs0; l1 += rs1;
        m0 = mn0; m1 = mn1;

        // ---- O += P V (S C-frag IS P A-frag; 3-term split) ----
        #pragma unroll
        for (int kk = 0; kk < 4; kk++) {
            const int n0 = 2 * kk;
            float h0, lo0, h1, lo1;
            uint32_t ph[4], pl[4];
            split_bf16(s[n0][0], h0, lo0);  split_bf16(s[n0][1], h1, lo1);
            ph[0] = pack_bf16(h0, h1);      pl[0] = pack_bf16(lo0, lo1);
            split_bf16(s[n0][2], h0, lo0);  split_bf16(s[n0][3], h1, lo1);
            ph[1] = pack_bf16(h0, h1);      pl[1] = pack_bf16(lo0, lo1);
            split_bf16(s[n0 + 1][0], h0, lo0);  split_bf16(s[n0 + 1][1], h1, lo1);
            ph[2] = pack_bf16(h0, h1);      pl[2] = pack_bf16(lo0, lo1);
            split_bf16(s[n0 + 1][2], h0, lo0);  split_bf16(s[n0 + 1][3], h1, lo1);
            ph[3] = pack_bf16(h0, h1);      pl[3] = pack_bf16(lo0, lo1);

            const int r0w = (8 * kk + t) * VW_STRIDE;
            const int r1w = (8 * kk + t + 4) * VW_STRIDE;
            #pragma unroll
            for (int na = 0; na < 8; na++) {
                int col = na * 8 + g;
                uint32_t bh0 = Vph[r0w + col], bh1 = Vph[r1w + col];
                uint32_t bl0 = Vpl[r0w + col], bl1 = Vpl[r1w + col];
                mma_bf16_16x8x16(o[na][0], o[na][1], o[na][2], o[na][3],
                                 ph[0], ph[1], ph[2], ph[3], bh0, bh1);
                mma_bf16_16x8x16(o[na][0], o[na][1], o[na][2], o[na][3],
                                 pl[0], pl[1], pl[2], pl[3], bh0, bh1);
                mma_bf16_16x8x16(o[na][0], o[na][1], o[na][2], o[na][3],
                                 ph[0], ph[1], ph[2], ph[3], bl0, bl1);
            }
        }
        __syncthreads();
    }

    const float inv0 = 1.f / l0, inv1 = 1.f / l1;
    const long ob0 = (long)(b * SEQ + row0) * EMB + hoff;
    const long ob1 = ob0 + 8L * EMB;
    #pragma unroll
    for (int na = 0; na < 8; na++) {
        int col = na * 8 + 2 * t;
        float2 w0 = make_float2(o[na][0] * inv0, o[na][1] * inv0);
        float2 w1 = make_float2(o[na][2] * inv1, o[na][3] * inv1);
        *reinterpret_cast<float2*>(g_attn + ob0 + col) = w0;
        *reinterpret_cast<float2*>(g_attn + ob1 + col) = w1;
    }
}

// ---------------------------------------------------------------------------
// Launch: five kernel launches, nothing else.
// ---------------------------------------------------------------------------
extern "C" void kernel_launch(void* const* d_in, const int* in_sizes, int n_in,
                              void* d_out, int out_size)
{
    const float* hidden = (const float*)d_in[0];
    const float* w_attn = (const float*)d_in[1];
    const float* b_attn = (const float*)d_in[2];
    const float* w_proj = (const float*)d_in[3];
    const float* b_proj = (const float*)d_in[4];
    float* out = (float*)d_out;

    // 1) QKV projection (tf32 TC, R6 layout) -> g_qkv
    qkv_tf32_kernel<<<dim3(QKV_N / 128, ROWS / 128), 256>>>(hidden, w_attn, b_attn);

    // 2) Presplit K/V into bf16 hi/lo packed word layout
    presplit_k_kernel<<<ROWS, 256>>>();
    presplit_v_kernel<<<ROWS / 2, 256>>>();

    // 3) Causal MHA, bf16-split MMA flash attention -> g_attn
    flash_attn_mma_kernel<<<dim3(SEQ / 128, HEADS, BATCH), 256>>>();

    // 4) Output projection (tf32 TC, R6 layout) -> out
    proj_tf32_kernel<<<dim3(EMB / 128, ROWS / 128), 256>>>(w_proj, b_proj, out);
}

// round 12
// speedup vs baseline: 1.1801x; 1.0181x over previous
#include <cuda_runtime.h>
#include <cuda_bf16.h>
#include <math.h>
#include <stdint.h>

// ---------------------------------------------------------------------------
// Problem constants: B=2, S=2048, E=1024, H=16, D=64
// ---------------------------------------------------------------------------
#define BATCH 2
#define SEQ   2048
#define EMB   1024
#define HEADS 16
#define HDIM  64
#define ROWS  (BATCH * SEQ)        // 4096
#define QKV_N (3 * EMB)            // 3072

// Scratch (allocation-free rule: __device__ globals)
__device__ float    g_qkv[ROWS * QKV_N];                    // 48 MB
__device__ float    g_attn[ROWS * EMB];                     // 16 MB
// Pre-split K/V in attention-smem word layout (bf16 hi/lo packed pairs)
__device__ uint32_t g_kh[BATCH * HEADS * SEQ * 32];         // 8 MB
__device__ uint32_t g_kl[BATCH * HEADS * SEQ * 32];         // 8 MB
__device__ uint32_t g_vh[BATCH * HEADS * (SEQ / 2) * 64];   // 8 MB
__device__ uint32_t g_vl[BATCH * HEADS * (SEQ / 2) * 64];   // 8 MB

// ---------------------------------------------------------------------------
// helpers
// ---------------------------------------------------------------------------
__device__ __forceinline__ uint32_t f32_to_tf32(float x) {
    uint32_t r;
    asm("cvt.rna.tf32.f32 %0, %1;" : "=r"(r) : "f"(x));
    return r;
}

__device__ __forceinline__ void mma_tf32_16x8x8(
    float& c0, float& c1, float& c2, float& c3,
    uint32_t a0, uint32_t a1, uint32_t a2, uint32_t a3,
    uint32_t b0, uint32_t b1)
{
    asm volatile(
        "mma.sync.aligned.m16n8k8.row.col.f32.tf32.tf32.f32 "
        "{%0,%1,%2,%3}, {%4,%5,%6,%7}, {%8,%9}, {%0,%1,%2,%3};"
        : "+f"(c0), "+f"(c1), "+f"(c2), "+f"(c3)
        : "r"(a0), "r"(a1), "r"(a2), "r"(a3), "r"(b0), "r"(b1));
}

__device__ __forceinline__ void mma_bf16_16x8x16(
    float& c0, float& c1, float& c2, float& c3,
    uint32_t a0, uint32_t a1, uint32_t a2, uint32_t a3,
    uint32_t b0, uint32_t b1)
{
    asm volatile(
        "mma.sync.aligned.m16n8k16.row.col.f32.bf16.bf16.f32 "
        "{%0,%1,%2,%3}, {%4,%5,%6,%7}, {%8,%9}, {%0,%1,%2,%3};"
        : "+f"(c0), "+f"(c1), "+f"(c2), "+f"(c3)
        : "r"(a0), "r"(a1), "r"(a2), "r"(a3), "r"(b0), "r"(b1));
}

__device__ __forceinline__ uint32_t pack_bf16(float a, float b) {
    __nv_bfloat162 p = __floats2bfloat162_rn(a, b);
    return *reinterpret_cast<uint32_t*>(&p);
}

__device__ __forceinline__ void split_bf16(float x, float& h, float& l) {
    h = __bfloat162float(__float2bfloat16_rn(x));
    l = x - h;
}

// ---------------------------------------------------------------------------
// tf32 tensor-core GEMM with fused bias — R6/R9 version (fill-time cvt,
// BK=32, A stride 36 / B stride 136). Measured 218us (QKV) / ~70us (proj).
// ---------------------------------------------------------------------------
template<int N, int K>
__device__ __forceinline__ void gemm_tf32(
    const float* __restrict__ A, const float* __restrict__ Bw,
    const float* __restrict__ bias, float* __restrict__ C)
{
    constexpr int BM = 128, BN = 128, BK = 32;
    constexpr int AS = BK + 4;
    constexpr int BS = BN + 8;

    __shared__ uint32_t As[BM * AS];
    __shared__ uint32_t Bs[BK * BS];

    const int tid    = threadIdx.x;
    const int lane   = tid & 31;
    const int wid    = tid >> 5;
    const int warp_m = wid >> 2;
    const int warp_n = wid & 3;
    const int g      = lane >> 2;
    const int t      = lane & 3;

    const int cRow = blockIdx.y * BM;
    const int cCol = blockIdx.x * BN;

    float acc[4][4][4];
    #pragma unroll
    for (int i = 0; i < 4; i++)
        #pragma unroll
        for (int j = 0; j < 4; j++)
            #pragma unroll
            for (int r = 0; r < 4; r++) acc[i][j][r] = 0.f;

    for (int k0 = 0; k0 < K; k0 += BK) {
        #pragma unroll
        for (int i = 0; i < 4; i++) {
            int idx = i * 256 + tid;
            int m   = idx >> 3;
            int c4  = (idx & 7) * 4;
            float4 v = *reinterpret_cast<const float4*>(
                A + (long)(cRow + m) * K + k0 + c4);
            As[m * AS + c4 + 0] = f32_to_tf32(v.x);
            As[m * AS + c4 + 1] = f32_to_tf32(v.y);
            As[m * AS + c4 + 2] = f32_to_tf32(v.z);
            As[m * AS + c4 + 3] = f32_to_tf32(v.w);
        }
        #pragma unroll
        for (int i = 0; i < 4; i++) {
            int idx = i * 256 + tid;
            int kr  = idx >> 5;
            int nc  = (idx & 31) * 4;
            float4 v = *reinterpret_cast<const float4*>(
                Bw + (long)(k0 + kr) * N + cCol + nc);
            Bs[kr * BS + nc + 0] = f32_to_tf32(v.x);
            Bs[kr * BS + nc + 1] = f32_to_tf32(v.y);
            Bs[kr * BS + nc + 2] = f32_to_tf32(v.z);
            Bs[kr * BS + nc + 3] = f32_to_tf32(v.w);
        }
        __syncthreads();

        #pragma unroll
        for (int kk = 0; kk < 4; kk++) {
            const int k8 = kk * 8;
            uint32_t a[4][4];
            #pragma unroll
            for (int ma = 0; ma < 4; ma++) {
                int row = warp_m * 64 + ma * 16;
                a[ma][0] = As[(row + g) * AS + k8 + t];
                a[ma][1] = As[(row + g + 8) * AS + k8 + t];
                a[ma][2] = As[(row + g) * AS + k8 + t + 4];
                a[ma][3] = As[(row + g + 8) * AS + k8 + t + 4];
            }
            uint32_t b[4][2];
            #pragma unroll
            for (int na = 0; na < 4; na++) {
                int col = warp_n * 32 + na * 8 + g;
                b[na][0] = Bs[(k8 + t) * BS + col];
                b[na][1] = Bs[(k8 + t + 4) * BS + col];
            }
            #pragma unroll
            for (int ma = 0; ma < 4; ma++)
                #pragma unroll
                for (int na = 0; na < 4; na++)
                    mma_tf32_16x8x8(acc[ma][na][0], acc[ma][na][1],
                                    acc[ma][na][2], acc[ma][na][3],
                                    a[ma][0], a[ma][1], a[ma][2], a[ma][3],
                                    b[na][0], b[na][1]);
        }
        __syncthreads();
    }

    #pragma unroll
    for (int ma = 0; ma < 4; ma++) {
        #pragma unroll
        for (int na = 0; na < 4; na++) {
            int row = cRow + warp_m * 64 + ma * 16 + g;
            int col = cCol + warp_n * 32 + na * 8 + 2 * t;
            float2 bv = *reinterpret_cast<const float2*>(bias + col);
            float2 v0, v1;
            v0.x = acc[ma][na][0] + bv.x;
            v0.y = acc[ma][na][1] + bv.y;
            v1.x = acc[ma][na][2] + bv.x;
            v1.y = acc[ma][na][3] + bv.y;
            *reinterpret_cast<float2*>(C + (long)row * N + col)       = v0;
            *reinterpret_cast<float2*>(C + (long)(row + 8) * N + col) = v1;
        }
    }
}

__global__ __launch_bounds__(256) void qkv_tf32_kernel(
    const float* __restrict__ A, const float* __restrict__ Bw,
    const float* __restrict__ bias)
{
    gemm_tf32<QKV_N, EMB>(A, Bw, bias, g_qkv);
}

__global__ __launch_bounds__(256) void proj_tf32_kernel(
    const float* __restrict__ Bw, const float* __restrict__ bias,
    float* __restrict__ C)
{
    gemm_tf32<EMB, EMB>(g_attn, Bw, bias, C);
}

// ---------------------------------------------------------------------------
// Presplit kernels (R10/R11, measured good).
// ---------------------------------------------------------------------------
__global__ __launch_bounds__(256) void presplit_k_kernel()
{
    const int r   = blockIdx.x;                // b*SEQ + s
    const int b   = r >> 11, s = r & (SEQ - 1);
    const int dg  = threadIdx.x * 4;           // 0..1020
    const int h   = dg >> 6, d = dg & 63;
    float4 v = *reinterpret_cast<const float4*>(g_qkv + (long)r * QKV_N + EMB + dg);
    float h0, l0, h1, l1, h2, l2, h3, l3;
    split_bf16(v.x, h0, l0); split_bf16(v.y, h1, l1);
    split_bf16(v.z, h2, l2); split_bf16(v.w, h3, l3);
    long o = ((long)(b * HEADS + h) * SEQ + s) * 32 + (d >> 1);
    *reinterpret_cast<uint2*>(g_kh + o) = make_uint2(pack_bf16(h0, h1), pack_bf16(h2, h3));
    *reinterpret_cast<uint2*>(g_kl + o) = make_uint2(pack_bf16(l0, l1), pack_bf16(l2, l3));
}

__global__ __launch_bounds__(256) void presplit_v_kernel()
{
    const int p   = blockIdx.x;                // b*(SEQ/2) + sp
    const int b   = p >> 10, sp = p & (SEQ / 2 - 1);
    const int dg  = threadIdx.x * 4;
    const int h   = dg >> 6, d = dg & 63;
    const long rbase = (long)(b * SEQ + 2 * sp) * QKV_N + 2 * EMB + dg;
    float4 v0 = *reinterpret_cast<const float4*>(g_qkv + rbase);
    float4 v1 = *reinterpret_cast<const float4*>(g_qkv + rbase + QKV_N);
    float ha, la, hb, lb;
    uint4 oh, ol;
    split_bf16(v0.x, ha, la); split_bf16(v1.x, hb, lb);
    oh.x = pack_bf16(ha, hb); ol.x = pack_bf16(la, lb);
    split_bf16(v0.y, ha, la); split_bf16(v1.y, hb, lb);
    oh.y = pack_bf16(ha, hb); ol.y = pack_bf16(la, lb);
    split_bf16(v0.z, ha, la); split_bf16(v1.z, hb, lb);
    oh.z = pack_bf16(ha, hb); ol.z = pack_bf16(la, lb);
    split_bf16(v0.w, ha, la); split_bf16(v1.w, hb, lb);
    oh.w = pack_bf16(ha, hb); ol.w = pack_bf16(la, lb);
    long o = ((long)(b * HEADS + h) * (SEQ / 2) + sp) * 64 + d;
    *reinterpret_cast<uint4*>(g_vh + o) = oh;
    *reinterpret_cast<uint4*>(g_vl + o) = ol;
}

// ---------------------------------------------------------------------------
// Flash attention: bf16 split m16n8k16, register-prefetch fills from
// pre-split gmem. R12 change: TERM-OUTER mma ordering — per kk-step the
// three split terms are issued as separate passes across all 8 independent
// accumulators, breaking the distance-1 RAW chains of the R11 ordering.
// ---------------------------------------------------------------------------
#define KW_STRIDE 36   // words per key row (32 dim-pairs + 4 pad)
#define VW_STRIDE 72   // words per key-pair row (64 dims + 8 pad)

__global__ __launch_bounds__(256) void flash_attn_mma_kernel()
{
    const int qt   = (int)gridDim.x - 1 - (int)blockIdx.x;  // heavy blocks first
    const int h    = blockIdx.y;
    const int b    = blockIdx.z;
    const int tid  = threadIdx.x;
    const int lane = tid & 31;
    const int w    = tid >> 5;
    const int g    = lane >> 2;   // 0..7
    const int t    = lane & 3;    // 0..3

    const int qbase = qt * 128;
    const int row0  = qbase + w * 16 + g;
    const int hoff  = h * HDIM;

    __shared__ uint32_t Kh[64 * KW_STRIDE];
    __shared__ uint32_t Kl[64 * KW_STRIDE];
    __shared__ uint32_t Vph[32 * VW_STRIDE];
    __shared__ uint32_t Vpl[32 * VW_STRIDE];

    uint32_t qh[4][4], ql[4][4];
    {
        const long r0 = (long)(b * SEQ + row0) * QKV_N + hoff;
        const long r1 = r0 + 8L * QKV_N;
        #pragma unroll
        for (int kk = 0; kk < 4; kk++) {
            int d0 = kk * 16 + 2 * t;
            int d1 = d0 + 8;
            float hx, lx, hy, ly;
            split_bf16(g_qkv[r0 + d0] * 0.125f, hx, lx);
            split_bf16(g_qkv[r0 + d0 + 1] * 0.125f, hy, ly);
            qh[kk][0] = pack_bf16(hx, hy);  ql[kk][0] = pack_bf16(lx, ly);
            split_bf16(g_qkv[r1 + d0] * 0.125f, hx, lx);
            split_bf16(g_qkv[r1 + d0 + 1] * 0.125f, hy, ly);
            qh[kk][1] = pack_bf16(hx, hy);  ql[kk][1] = pack_bf16(lx, ly);
            split_bf16(g_qkv[r0 + d1] * 0.125f, hx, lx);
            split_bf16(g_qkv[r0 + d1 + 1] * 0.125f, hy, ly);
            qh[kk][2] = pack_bf16(hx, hy);  ql[kk][2] = pack_bf16(lx, ly);
            split_bf16(g_qkv[r1 + d1] * 0.125f, hx, lx);
            split_bf16(g_qkv[r1 + d1 + 1] * 0.125f, hy, ly);
            qh[kk][3] = pack_bf16(hx, hy);  ql[kk][3] = pack_bf16(lx, ly);
        }
    }

    float o[8][4];
    #pragma unroll
    for (int na = 0; na < 8; na++)
        #pragma unroll
        for (int e = 0; e < 4; e++) o[na][e] = 0.f;
    float m0 = -INFINITY, m1 = -INFINITY, l0 = 0.f, l1 = 0.f;

    // prefetch registers (8 uint4 = 32 regs)
    uint4 pkh[2], pkl[2], pvh[2], pvl[2];

    const long khbase = (long)(b * HEADS + h) * SEQ * 32;
    const long vbase0 = (long)(b * HEADS + h) * (SEQ / 2) * 64;

    auto ldg_tile = [&](int kt) {
        const long kb = khbase + (long)kt * 64 * 32;
        #pragma unroll
        for (int i = 0; i < 2; i++) {
            int idx = i * 256 + tid;
            int j   = idx >> 3;            // key row 0..63
            int wq  = idx & 7;             // uint4 within row
            pkh[i] = *reinterpret_cast<const uint4*>(g_kh + kb + j * 32 + wq * 4);
            pkl[i] = *reinterpret_cast<const uint4*>(g_kl + kb + j * 32 + wq * 4);
        }
        const long vb = vbase0 + (long)kt * 32 * 64;
        #pragma unroll
        for (int i = 0; i < 2; i++) {
            int idx = i * 256 + tid;
            int jp  = idx >> 4;            // pair row 0..31
            int wq  = idx & 15;
            pvh[i] = *reinterpret_cast<const uint4*>(g_vh + vb + jp * 64 + wq * 4);
            pvl[i] = *reinterpret_cast<const uint4*>(g_vl + vb + jp * 64 + wq * 4);
        }
    };

    const int ntiles = 2 * qt + 2;
    ldg_tile(0);

    for (int kt = 0; kt < ntiles; kt++) {
        // ---- STS from prefetched registers (no conversion) ----
        #pragma unroll
        for (int i = 0; i < 2; i++) {
            int idx = i * 256 + tid;
            int j   = idx >> 3;
            int wq  = idx & 7;
            *reinterpret_cast<uint4*>(&Kh[j * KW_STRIDE + wq * 4]) = pkh[i];
            *reinterpret_cast<uint4*>(&Kl[j * KW_STRIDE + wq * 4]) = pkl[i];
        }
        #pragma unroll
        for (int i = 0; i < 2; i++) {
            int idx = i * 256 + tid;
            int jp  = idx >> 4;
            int wq  = idx & 15;
            *reinterpret_cast<uint4*>(&Vph[jp * VW_STRIDE + wq * 4]) = pvh[i];
            *reinterpret_cast<uint4*>(&Vpl[jp * VW_STRIDE + wq * 4]) = pvl[i];
        }
        __syncthreads();

        // ---- prefetch next tile (overlaps mma phase) ----
        if (kt + 1 < ntiles) ldg_tile(kt + 1);

        // ---- scores S = Q K^T (3-term bf16 split, TERM-OUTER) ----
        float s[8][4];
        #pragma unroll
        for (int na = 0; na < 8; na++)
            #pragma unroll
            for (int e = 0; e < 4; e++) s[na][e] = 0.f;

        #pragma unroll
        for (int kk = 0; kk < 4; kk++) {
            const int w0 = kk * 8 + t;
            uint32_t kb[8][2];
            #pragma unroll
            for (int na = 0; na < 8; na++) {
                int key = na * 8 + g;
                kb[na][0] = Kh[key * KW_STRIDE + w0];
                kb[na][1] = Kh[key * KW_STRIDE + w0 + 4];
            }
            #pragma unroll
            for (int na = 0; na < 8; na++)
                mma_bf16_16x8x16(s[na][0], s[na][1], s[na][2], s[na][3],
                                 qh[kk][0], qh[kk][1], qh[kk][2], qh[kk][3],
                                 kb[na][0], kb[na][1]);
            #pragma unroll
            for (int na = 0; na < 8; na++)
                mma_bf16_16x8x16(s[na][0], s[na][1], s[na][2], s[na][3],
                                 ql[kk][0], ql[kk][1], ql[kk][2], ql[kk][3],
                                 kb[na][0], kb[na][1]);
            #pragma unroll
            for (int na = 0; na < 8; na++) {
                int key = na * 8 + g;
                kb[na][0] = Kl[key * KW_STRIDE + w0];
                kb[na][1] = Kl[key * KW_STRIDE + w0 + 4];
            }
            #pragma unroll
            for (int na = 0; na < 8; na++)
                mma_bf16_16x8x16(s[na][0], s[na][1], s[na][2], s[na][3],
                                 qh[kk][0], qh[kk][1], qh[kk][2], qh[kk][3],
                                 kb[na][0], kb[na][1]);
        }

        // ---- causal mask (diagonal tiles only) ----
        if (kt >= 2 * qt) {
            const int colbase = kt * 64 + 2 * t;
            #pragma unroll
            for (int na = 0; na < 8; na++) {
                int c = colbase + 8 * na;
                if (c     > row0)     s[na][0] = -INFINITY;
                if (c + 1 > row0)     s[na][1] = -INFINITY;
                if (c     > row0 + 8) s[na][2] = -INFINITY;
                if (c + 1 > row0 + 8) s[na][3] = -INFINITY;
            }
        }

        // ---- online softmax ----
        float tm0 = -INFINITY, tm1 = -INFINITY;
        #pragma unroll
        for (int na = 0; na < 8; na++) {
            tm0 = fmaxf(tm0, fmaxf(s[na][0], s[na][1]));
            tm1 = fmaxf(tm1, fmaxf(s[na][2], s[na][3]));
        }
        tm0 = fmaxf(tm0, __shfl_xor_sync(0xffffffffu, tm0, 1));
        tm0 = fmaxf(tm0, __shfl_xor_sync(0xffffffffu, tm0, 2));
        tm1 = fmaxf(tm1, __shfl_xor_sync(0xffffffffu, tm1, 1));
        tm1 = fmaxf(tm1, __shfl_xor_sync(0xffffffffu, tm1, 2));

        float mn0 = fmaxf(m0, tm0), mn1 = fmaxf(m1, tm1);
        float a0 = __expf(m0 - mn0), a1 = __expf(m1 - mn1);
        l0 *= a0; l1 *= a1;
        #pragma unroll
        for (int na = 0; na < 8; na++) {
            o[na][0] *= a0; o[na][1] *= a0;
            o[na][2] *= a1; o[na][3] *= a1;
        }

        float rs0 = 0.f, rs1 = 0.f;
        #pragma unroll
        for (int na = 0; na < 8; na++) {
            s[na][0] = __expf(s[na][0] - mn0);
            s[na][1] = __expf(s[na][1] - mn0);
            s[na][2] = __expf(s[na][2] - mn1);
            s[na][3] = __expf(s[na][3] - mn1);
            rs0 += s[na][0] + s[na][1];
            rs1 += s[na][2] + s[na][3];
        }
        rs0 += __shfl_xor_sync(0xffffffffu, rs0, 1);
        rs0 += __shfl_xor_sync(0xffffffffu, rs0, 2);
        rs1 += __shfl_xor_sync(0xffffffffu, rs1, 1);
        rs1 += __shfl_xor_sync(0xffffffffu, rs1, 2);
        l0 += rs0; l1 += rs1;
        m0 = mn0; m1 = mn1;

        // ---- O += P V (S C-frag IS P A-frag; 3-term split, TERM-OUTER) ----
        #pragma unroll
        for (int kk = 0; kk < 4; kk++) {
            const int n0 = 2 * kk;
            float h0, lo0, h1, lo1;
            uint32_t ph[4], pl[4];
            split_bf16(s[n0][0], h0, lo0);  split_bf16(s[n0][1], h1, lo1);
            ph[0] = pack_bf16(h0, h1);      pl[0] = pack_bf16(lo0, lo1);
            split_bf16(s[n0][2], h0, lo0);  split_bf16(s[n0][3], h1, lo1);
            ph[1] = pack_bf16(h0, h1);      pl[1] = pack_bf16(lo0, lo1);
            split_bf16(s[n0 + 1][0], h0, lo0);  split_bf16(s[n0 + 1][1], h1, lo1);
            ph[2] = pack_bf16(h0, h1);      pl[2] = pack_bf16(lo0, lo1);
            split_bf16(s[n0 + 1][2], h0, lo0);  split_bf16(s[n0 + 1][3], h1, lo1);
            ph[3] = pack_bf16(h0, h1);      pl[3] = pack_bf16(lo0, lo1);

            const int r0w = (8 * kk + t) * VW_STRIDE;
            const int r1w = (8 * kk + t + 4) * VW_STRIDE;
            uint32_t vb[8][2];
            #pragma unroll
            for (int na = 0; na < 8; na++) {
                int col = na * 8 + g;
                vb[na][0] = Vph[r0w + col];
                vb[na][1] = Vph[r1w + col];
            }
            #pragma unroll
            for (int na = 0; na < 8; na++)
                mma_bf16_16x8x16(o[na][0], o[na][1], o[na][2], o[na][3],
                                 ph[0], ph[1], ph[2], ph[3], vb[na][0], vb[na][1]);
            #pragma unroll
            for (int na = 0; na < 8; na++)
                mma_bf16_16x8x16(o[na][0], o[na][1], o[na][2], o[na][3],
                                 pl[0], pl[1], pl[2], pl[3], vb[na][0], vb[na][1]);
            #pragma unroll
            for (int na = 0; na < 8; na++) {
                int col = na * 8 + g;
                vb[na][0] = Vpl[r0w + col];
                vb[na][1] = Vpl[r1w + col];
            }
            #pragma unroll
            for (int na = 0; na < 8; na++)
                mma_bf16_16x8x16(o[na][0], o[na][1], o[na][2], o[na][3],
                                 ph[0], ph[1], ph[2], ph[3], vb[na][0], vb[na][1]);
        }
        __syncthreads();
    }

    const float inv0 = 1.f / l0, inv1 = 1.f / l1;
    const long ob0 = (long)(b * SEQ + row0) * EMB + hoff;
    const long ob1 = ob0 + 8L * EMB;
    #pragma unroll
    for (int na = 0; na < 8; na++) {
        int col = na * 8 + 2 * t;
        float2 w0 = make_float2(o[na][0] * inv0, o[na][1] * inv0);
        float2 w1 = make_float2(o[na][2] * inv1, o[na][3] * inv1);
        *reinterpret_cast<float2*>(g_attn + ob0 + col) = w0;
        *reinterpret_cast<float2*>(g_attn + ob1 + col) = w1;
    }
}

// ---------------------------------------------------------------------------
// Launch: five kernel launches, nothing else.
// ---------------------------------------------------------------------------
extern "C" void kernel_launch(void* const* d_in, const int* in_sizes, int n_in,
                              void* d_out, int out_size)
{
    const float* hidden = (const float*)d_in[0];
    const float* w_attn = (const float*)d_in[1];
    const float* b_attn = (const float*)d_in[2];
    const float* w_proj = (const float*)d_in[3];
    const float* b_proj = (const float*)d_in[4];
    float* out = (float*)d_out;

    // 1) QKV projection (tf32 TC) -> g_qkv
    qkv_tf32_kernel<<<dim3(QKV_N / 128, ROWS / 128), 256>>>(hidden, w_attn, b_attn);

    // 2) Presplit K/V into bf16 hi/lo packed word layout
    presplit_k_kernel<<<ROWS, 256>>>();
    presplit_v_kernel<<<ROWS / 2, 256>>>();

    // 3) Causal MHA, bf16-split MMA flash attention (term-outer) -> g_attn
    flash_attn_mma_kernel<<<dim3(SEQ / 128, HEADS, BATCH), 256>>>();

    // 4) Output projection (tf32 TC) -> out
    proj_tf32_kernel<<<dim3(EMB / 128, ROWS / 128), 256>>>(w_proj, b_proj, out);
}

// round 14
// speedup vs baseline: 1.1902x; 1.0085x over previous
#include <cuda_runtime.h>
#include <cuda_bf16.h>
#include <math.h>
#include <stdint.h>

// ---------------------------------------------------------------------------
// Problem constants: B=2, S=2048, E=1024, H=16, D=64
// ---------------------------------------------------------------------------
#define BATCH 2
#define SEQ   2048
#define EMB   1024
#define HEADS 16
#define HDIM  64
#define ROWS  (BATCH * SEQ)        // 4096
#define QKV_N (3 * EMB)            // 3072

// Scratch (allocation-free rule: __device__ globals)
__device__ float    g_qkv[ROWS * QKV_N];                    // 48 MB
__device__ float    g_attn[ROWS * EMB];                     // 16 MB
// Pre-split K/V in attention-smem word layout (bf16 hi/lo packed pairs)
__device__ uint32_t g_kh[BATCH * HEADS * SEQ * 32];         // 8 MB
__device__ uint32_t g_kl[BATCH * HEADS * SEQ * 32];         // 8 MB
__device__ uint32_t g_vh[BATCH * HEADS * (SEQ / 2) * 64];   // 8 MB
__device__ uint32_t g_vl[BATCH * HEADS * (SEQ / 2) * 64];   // 8 MB

// ---------------------------------------------------------------------------
// helpers
// ---------------------------------------------------------------------------
__device__ __forceinline__ uint32_t f32_to_tf32(float x) {
    uint32_t r;
    asm("cvt.rna.tf32.f32 %0, %1;" : "=r"(r) : "f"(x));
    return r;
}

__device__ __forceinline__ void mma_tf32_16x8x8(
    float& c0, float& c1, float& c2, float& c3,
    uint32_t a0, uint32_t a1, uint32_t a2, uint32_t a3,
    uint32_t b0, uint32_t b1)
{
    asm volatile(
        "mma.sync.aligned.m16n8k8.row.col.f32.tf32.tf32.f32 "
        "{%0,%1,%2,%3}, {%4,%5,%6,%7}, {%8,%9}, {%0,%1,%2,%3};"
        : "+f"(c0), "+f"(c1), "+f"(c2), "+f"(c3)
        : "r"(a0), "r"(a1), "r"(a2), "r"(a3), "r"(b0), "r"(b1));
}

__device__ __forceinline__ void mma_bf16_16x8x16(
    float& c0, float& c1, float& c2, float& c3,
    uint32_t a0, uint32_t a1, uint32_t a2, uint32_t a3,
    uint32_t b0, uint32_t b1)
{
    asm volatile(
        "mma.sync.aligned.m16n8k16.row.col.f32.bf16.bf16.f32 "
        "{%0,%1,%2,%3}, {%4,%5,%6,%7}, {%8,%9}, {%0,%1,%2,%3};"
        : "+f"(c0), "+f"(c1), "+f"(c2), "+f"(c3)
        : "r"(a0), "r"(a1), "r"(a2), "r"(a3), "r"(b0), "r"(b1));
}

__device__ __forceinline__ uint32_t pack_bf16(float a, float b) {
    __nv_bfloat162 p = __floats2bfloat162_rn(a, b);
    return *reinterpret_cast<uint32_t*>(&p);
}

__device__ __forceinline__ void split_bf16(float x, float& h, float& l) {
    h = __bfloat162float(__float2bfloat16_rn(x));
    l = x - h;
}

__device__ __forceinline__ void cp_async16(void* smem, const void* gmem) {
    uint32_t saddr = (uint32_t)__cvta_generic_to_shared(smem);
    asm volatile("cp.async.cg.shared.global [%0], [%1], 16;"
                 :: "r"(saddr), "l"(gmem));
}
__device__ __forceinline__ void cp_commit() {
    asm volatile("cp.async.commit_group;");
}
__device__ __forceinline__ void cp_wait0() {
    asm volatile("cp.async.wait_group 0;");
}

// ---------------------------------------------------------------------------
// tf32 tensor-core GEMM with fused bias — R6/R9 version (unchanged, passing).
// ---------------------------------------------------------------------------
template<int N, int K>
__device__ __forceinline__ void gemm_tf32(
    const float* __restrict__ A, const float* __restrict__ Bw,
    const float* __restrict__ bias, float* __restrict__ C)
{
    constexpr int BM = 128, BN = 128, BK = 32;
    constexpr int AS = BK + 4;
    constexpr int BS = BN + 8;

    __shared__ uint32_t As[BM * AS];
    __shared__ uint32_t Bs[BK * BS];

    const int tid    = threadIdx.x;
    const int lane   = tid & 31;
    const int wid    = tid >> 5;
    const int warp_m = wid >> 2;
    const int warp_n = wid & 3;
    const int g      = lane >> 2;
    const int t      = lane & 3;

    const int cRow = blockIdx.y * BM;
    const int cCol = blockIdx.x * BN;

    float acc[4][4][4];
    #pragma unroll
    for (int i = 0; i < 4; i++)
        #pragma unroll
        for (int j = 0; j < 4; j++)
            #pragma unroll
            for (int r = 0; r < 4; r++) acc[i][j][r] = 0.f;

    for (int k0 = 0; k0 < K; k0 += BK) {
        #pragma unroll
        for (int i = 0; i < 4; i++) {
            int idx = i * 256 + tid;
            int m   = idx >> 3;
            int c4  = (idx & 7) * 4;
            float4 v = *reinterpret_cast<const float4*>(
                A + (long)(cRow + m) * K + k0 + c4);
            As[m * AS + c4 + 0] = f32_to_tf32(v.x);
            As[m * AS + c4 + 1] = f32_to_tf32(v.y);
            As[m * AS + c4 + 2] = f32_to_tf32(v.z);
            As[m * AS + c4 + 3] = f32_to_tf32(v.w);
        }
        #pragma unroll
        for (int i = 0; i < 4; i++) {
            int idx = i * 256 + tid;
            int kr  = idx >> 5;
            int nc  = (idx & 31) * 4;
            float4 v = *reinterpret_cast<const float4*>(
                Bw + (long)(k0 + kr) * N + cCol + nc);
            Bs[kr * BS + nc + 0] = f32_to_tf32(v.x);
            Bs[kr * BS + nc + 1] = f32_to_tf32(v.y);
            Bs[kr * BS + nc + 2] = f32_to_tf32(v.z);
            Bs[kr * BS + nc + 3] = f32_to_tf32(v.w);
        }
        __syncthreads();

        #pragma unroll
        for (int kk = 0; kk < 4; kk++) {
            const int k8 = kk * 8;
            uint32_t a[4][4];
            #pragma unroll
            for (int ma = 0; ma < 4; ma++) {
                int row = warp_m * 64 + ma * 16;
                a[ma][0] = As[(row + g) * AS + k8 + t];
                a[ma][1] = As[(row + g + 8) * AS + k8 + t];
                a[ma][2] = As[(row + g) * AS + k8 + t + 4];
                a[ma][3] = As[(row + g + 8) * AS + k8 + t + 4];
            }
            uint32_t b[4][2];
            #pragma unroll
            for (int na = 0; na < 4; na++) {
                int col = warp_n * 32 + na * 8 + g;
                b[na][0] = Bs[(k8 + t) * BS + col];
                b[na][1] = Bs[(k8 + t + 4) * BS + col];
            }
            #pragma unroll
            for (int ma = 0; ma < 4; ma++)
                #pragma unroll
                for (int na = 0; na < 4; na++)
                    mma_tf32_16x8x8(acc[ma][na][0], acc[ma][na][1],
                                    acc[ma][na][2], acc[ma][na][3],
                                    a[ma][0], a[ma][1], a[ma][2], a[ma][3],
                                    b[na][0], b[na][1]);
        }
        __syncthreads();
    }

    #pragma unroll
    for (int ma = 0; ma < 4; ma++) {
        #pragma unroll
        for (int na = 0; na < 4; na++) {
            int row = cRow + warp_m * 64 + ma * 16 + g;
            int col = cCol + warp_n * 32 + na * 8 + 2 * t;
            float2 bv = *reinterpret_cast<const float2*>(bias + col);
            float2 v0, v1;
            v0.x = acc[ma][na][0] + bv.x;
            v0.y = acc[ma][na][1] + bv.y;
            v1.x = acc[ma][na][2] + bv.x;
            v1.y = acc[ma][na][3] + bv.y;
            *reinterpret_cast<float2*>(C + (long)row * N + col)       = v0;
            *reinterpret_cast<float2*>(C + (long)(row + 8) * N + col) = v1;
        }
    }
}

__global__ __launch_bounds__(256) void qkv_tf32_kernel(
    const float* __restrict__ A, const float* __restrict__ Bw,
    const float* __restrict__ bias)
{
    gemm_tf32<QKV_N, EMB>(A, Bw, bias, g_qkv);
}

__global__ __launch_bounds__(256) void proj_tf32_kernel(
    const float* __restrict__ Bw, const float* __restrict__ bias,
    float* __restrict__ C)
{
    gemm_tf32<EMB, EMB>(g_attn, Bw, bias, C);
}

// ---------------------------------------------------------------------------
// Presplit kernels (unchanged, passing).
// ---------------------------------------------------------------------------
__global__ __launch_bounds__(256) void presplit_k_kernel()
{
    const int r   = blockIdx.x;
    const int b   = r >> 11, s = r & (SEQ - 1);
    const int dg  = threadIdx.x * 4;
    const int h   = dg >> 6, d = dg & 63;
    float4 v = *reinterpret_cast<const float4*>(g_qkv + (long)r * QKV_N + EMB + dg);
    float h0, l0, h1, l1, h2, l2, h3, l3;
    split_bf16(v.x, h0, l0); split_bf16(v.y, h1, l1);
    split_bf16(v.z, h2, l2); split_bf16(v.w, h3, l3);
    long o = ((long)(b * HEADS + h) * SEQ + s) * 32 + (d >> 1);
    *reinterpret_cast<uint2*>(g_kh + o) = make_uint2(pack_bf16(h0, h1), pack_bf16(h2, h3));
    *reinterpret_cast<uint2*>(g_kl + o) = make_uint2(pack_bf16(l0, l1), pack_bf16(l2, l3));
}

__global__ __launch_bounds__(256) void presplit_v_kernel()
{
    const int p   = blockIdx.x;
    const int b   = p >> 10, sp = p & (SEQ / 2 - 1);
    const int dg  = threadIdx.x * 4;
    const int h   = dg >> 6, d = dg & 63;
    const long rbase = (long)(b * SEQ + 2 * sp) * QKV_N + 2 * EMB + dg;
    float4 v0 = *reinterpret_cast<const float4*>(g_qkv + rbase);
    float4 v1 = *reinterpret_cast<const float4*>(g_qkv + rbase + QKV_N);
    float ha, la, hb, lb;
    uint4 oh, ol;
    split_bf16(v0.x, ha, la); split_bf16(v1.x, hb, lb);
    oh.x = pack_bf16(ha, hb); ol.x = pack_bf16(la, lb);
    split_bf16(v0.y, ha, la); split_bf16(v1.y, hb, lb);
    oh.y = pack_bf16(ha, hb); ol.y = pack_bf16(la, lb);
    split_bf16(v0.z, ha, la); split_bf16(v1.z, hb, lb);
    oh.z = pack_bf16(ha, hb); ol.z = pack_bf16(la, lb);
    split_bf16(v0.w, ha, la); split_bf16(v1.w, hb, lb);
    oh.w = pack_bf16(ha, hb); ol.w = pack_bf16(la, lb);
    long o = ((long)(b * HEADS + h) * (SEQ / 2) + sp) * 64 + d;
    *reinterpret_cast<uint4*>(g_vh + o) = oh;
    *reinterpret_cast<uint4*>(g_vl + o) = ol;
}

// ---------------------------------------------------------------------------
// Flash attention R13: 32-key tiles, cp.async double-buffered smem,
// 2 CTAs/SM. Term-outer bf16-split mma (same math as R12).
// ---------------------------------------------------------------------------
#define KW_STRIDE 36   // words per key row (32 dim-pairs + 4 pad)
#define VW_STRIDE 72   // words per key-pair row (64 dims + 8 pad)
#define KTILE 32       // keys per tile

__global__ __launch_bounds__(256, 2) void flash_attn_mma_kernel()
{
    const int qt   = (int)gridDim.x - 1 - (int)blockIdx.x;  // heavy blocks first
    const int h    = blockIdx.y;
    const int b    = blockIdx.z;
    const int tid  = threadIdx.x;
    const int lane = tid & 31;
    const int w    = tid >> 5;
    const int g    = lane >> 2;   // 0..7
    const int t    = lane & 3;    // 0..3

    const int qbase = qt * 128;
    const int row0  = qbase + w * 16 + g;
    const int hoff  = h * HDIM;

    // double-buffered tiles: 36,864 B total (static, <48KB; 2 CTAs fit in SM)
    __shared__ uint32_t Kh[2][KTILE * KW_STRIDE];
    __shared__ uint32_t Kl[2][KTILE * KW_STRIDE];
    __shared__ uint32_t Vph[2][(KTILE / 2) * VW_STRIDE];
    __shared__ uint32_t Vpl[2][(KTILE / 2) * VW_STRIDE];

    uint32_t qh[4][4], ql[4][4];
    {
        const long r0 = (long)(b * SEQ + row0) * QKV_N + hoff;
        const long r1 = r0 + 8L * QKV_N;
        #pragma unroll
        for (int kk = 0; kk < 4; kk++) {
            int d0 = kk * 16 + 2 * t;
            int d1 = d0 + 8;
            float hx, lx, hy, ly;
            split_bf16(g_qkv[r0 + d0] * 0.125f, hx, lx);
            split_bf16(g_qkv[r0 + d0 + 1] * 0.125f, hy, ly);
            qh[kk][0] = pack_bf16(hx, hy);  ql[kk][0] = pack_bf16(lx, ly);
            split_bf16(g_qkv[r1 + d0] * 0.125f, hx, lx);
            split_bf16(g_qkv[r1 + d0 + 1] * 0.125f, hy, ly);
            qh[kk][1] = pack_bf16(hx, hy);  ql[kk][1] = pack_bf16(lx, ly);
            split_bf16(g_qkv[r0 + d1] * 0.125f, hx, lx);
            split_bf16(g_qkv[r0 + d1 + 1] * 0.125f, hy, ly);
            qh[kk][2] = pack_bf16(hx, hy);  ql[kk][2] = pack_bf16(lx, ly);
            split_bf16(g_qkv[r1 + d1] * 0.125f, hx, lx);
            split_bf16(g_qkv[r1 + d1 + 1] * 0.125f, hy, ly);
            qh[kk][3] = pack_bf16(hx, hy);  ql[kk][3] = pack_bf16(lx, ly);
        }
    }

    float o[8][4];
    #pragma unroll
    for (int na = 0; na < 8; na++)
        #pragma unroll
        for (int e = 0; e < 4; e++) o[na][e] = 0.f;
    float m0 = -INFINITY, m1 = -INFINITY, l0 = 0.f, l1 = 0.f;

    const long khbase = (long)(b * HEADS + h) * SEQ * 32;
    const long vbase0 = (long)(b * HEADS + h) * (SEQ / 2) * 64;

    // one cp.async per array per thread per tile (4 total)
    const int kj  = tid >> 3,  kc = (tid & 7) * 4;    // K: 32 rows x 8 chunks
    const int vj  = tid >> 4,  vc = (tid & 15) * 4;   // V: 16 rows x 16 chunks

    auto fill = [&](int kt, int bufi) {
        const long kb = khbase + (long)kt * KTILE * 32;
        cp_async16(&Kh[bufi][kj * KW_STRIDE + kc], g_kh + kb + kj * 32 + kc);
        cp_async16(&Kl[bufi][kj * KW_STRIDE + kc], g_kl + kb + kj * 32 + kc);
        const long vb = vbase0 + (long)kt * (KTILE / 2) * 64;
        cp_async16(&Vph[bufi][vj * VW_STRIDE + vc], g_vh + vb + vj * 64 + vc);
        cp_async16(&Vpl[bufi][vj * VW_STRIDE + vc], g_vl + vb + vj * 64 + vc);
        cp_commit();
    };

    const int ntiles = 4 * qt + 4;
    fill(0, 0);
    int buf = 0;

    for (int kt = 0; kt < ntiles; kt++) {
        cp_wait0();
        __syncthreads();
        if (kt + 1 < ntiles) fill(kt + 1, buf ^ 1);

        // ---- scores S = Q K^T (3-term bf16 split, term-outer) ----
        float s[4][4];
        #pragma unroll
        for (int na = 0; na < 4; na++)
            #pragma unroll
            for (int e = 0; e < 4; e++) s[na][e] = 0.f;

        #pragma unroll
        for (int kk = 0; kk < 4; kk++) {
            const int w0 = kk * 8 + t;
            uint32_t kb[4][2];
            #pragma unroll
            for (int na = 0; na < 4; na++) {
                int key = na * 8 + g;
                kb[na][0] = Kh[buf][key * KW_STRIDE + w0];
                kb[na][1] = Kh[buf][key * KW_STRIDE + w0 + 4];
            }
            #pragma unroll
            for (int na = 0; na < 4; na++)
                mma_bf16_16x8x16(s[na][0], s[na][1], s[na][2], s[na][3],
                                 qh[kk][0], qh[kk][1], qh[kk][2], qh[kk][3],
                                 kb[na][0], kb[na][1]);
            #pragma unroll
            for (int na = 0; na < 4; na++)
                mma_bf16_16x8x16(s[na][0], s[na][1], s[na][2], s[na][3],
                                 ql[kk][0], ql[kk][1], ql[kk][2], ql[kk][3],
                                 kb[na][0], kb[na][1]);
            #pragma unroll
            for (int na = 0; na < 4; na++) {
                int key = na * 8 + g;
                kb[na][0] = Kl[buf][key * KW_STRIDE + w0];
                kb[na][1] = Kl[buf][key * KW_STRIDE + w0 + 4];
            }
            #pragma unroll
            for (int na = 0; na < 4; na++)
                mma_bf16_16x8x16(s[na][0], s[na][1], s[na][2], s[na][3],
                                 qh[kk][0], qh[kk][1], qh[kk][2], qh[kk][3],
                                 kb[na][0], kb[na][1]);
        }

        // ---- causal mask (diagonal tiles: last 4) ----
        if (kt >= 4 * qt) {
            const int colbase = kt * KTILE + 2 * t;
            #pragma unroll
            for (int na = 0; na < 4; na++) {
                int c = colbase + 8 * na;
                if (c     > row0)     s[na][0] = -INFINITY;
                if (c + 1 > row0)     s[na][1] = -INFINITY;
                if (c     > row0 + 8) s[na][2] = -INFINITY;
                if (c + 1 > row0 + 8) s[na][3] = -INFINITY;
            }
        }

        // ---- online softmax ----
        float tm0 = -INFINITY, tm1 = -INFINITY;
        #pragma unroll
        for (int na = 0; na < 4; na++) {
            tm0 = fmaxf(tm0, fmaxf(s[na][0], s[na][1]));
            tm1 = fmaxf(tm1, fmaxf(s[na][2], s[na][3]));
        }
        tm0 = fmaxf(tm0, __shfl_xor_sync(0xffffffffu, tm0, 1));
        tm0 = fmaxf(tm0, __shfl_xor_sync(0xffffffffu, tm0, 2));
        tm1 = fmaxf(tm1, __shfl_xor_sync(0xffffffffu, tm1, 1));
        tm1 = fmaxf(tm1, __shfl_xor_sync(0xffffffffu, tm1, 2));

        float mn0 = fmaxf(m0, tm0), mn1 = fmaxf(m1, tm1);
        float a0 = __expf(m0 - mn0), a1 = __expf(m1 - mn1);
        l0 *= a0; l1 *= a1;
        #pragma unroll
        for (int na = 0; na < 8; na++) {
            o[na][0] *= a0; o[na][1] *= a0;
            o[na][2] *= a1; o[na][3] *= a1;
        }

        float rs0 = 0.f, rs1 = 0.f;
        #pragma unroll
        for (int na = 0; na < 4; na++) {
            s[na][0] = __expf(s[na][0] - mn0);
            s[na][1] = __expf(s[na][1] - mn0);
            s[na][2] = __expf(s[na][2] - mn1);
            s[na][3] = __expf(s[na][3] - mn1);
            rs0 += s[na][0] + s[na][1];
            rs1 += s[na][2] + s[na][3];
        }
        rs0 += __shfl_xor_sync(0xffffffffu, rs0, 1);
        rs0 += __shfl_xor_sync(0xffffffffu, rs0, 2);
        rs1 += __shfl_xor_sync(0xffffffffu, rs1, 1);
        rs1 += __shfl_xor_sync(0xffffffffu, rs1, 2);
        l0 += rs0; l1 += rs1;
        m0 = mn0; m1 = mn1;

        // ---- O += P V (S C-frag IS P A-frag; 3-term split, term-outer) ----
        #pragma unroll
        for (int kk = 0; kk < 2; kk++) {
            const int n0 = 2 * kk;
            float h0, lo0, h1, lo1;
            uint32_t ph[4], pl[4];
            split_bf16(s[n0][0], h0, lo0);  split_bf16(s[n0][1], h1, lo1);
            ph[0] = pack_bf16(h0, h1);      pl[0] = pack_bf16(lo0, lo1);
            split_bf16(s[n0][2], h0, lo0);  split_bf16(s[n0][3], h1, lo1);
            ph[1] = pack_bf16(h0, h1);      pl[1] = pack_bf16(lo0, lo1);
            split_bf16(s[n0 + 1][0], h0, lo0);  split_bf16(s[n0 + 1][1], h1, lo1);
            ph[2] = pack_bf16(h0, h1);      pl[2] = pack_bf16(lo0, lo1);
            split_bf16(s[n0 + 1][2], h0, lo0);  split_bf16(s[n0 + 1][3], h1, lo1);
            ph[3] = pack_bf16(h0, h1);      pl[3] = pack_bf16(lo0, lo1);

            const int r0w = (8 * kk + t) * VW_STRIDE;
            const int r1w = (8 * kk + t + 4) * VW_STRIDE;
            uint32_t vb[8][2];
            #pragma unroll
            for (int na = 0; na < 8; na++) {
                int col = na * 8 + g;
                vb[na][0] = Vph[buf][r0w + col];
                vb[na][1] = Vph[buf][r1w + col];
            }
            #pragma unroll
            for (int na = 0; na < 8; na++)
                mma_bf16_16x8x16(o[na][0], o[na][1], o[na][2], o[na][3],
                                 ph[0], ph[1], ph[2], ph[3], vb[na][0], vb[na][1]);
            #pragma unroll
            for (int na = 0; na < 8; na++)
                mma_bf16_16x8x16(o[na][0], o[na][1], o[na][2], o[na][3],
                                 pl[0], pl[1], pl[2], pl[3], vb[na][0], vb[na][1]);
            #pragma unroll
            for (int na = 0; na < 8; na++) {
                int col = na * 8 + g;
                vb[na][0] = Vpl[buf][r0w + col];
                vb[na][1] = Vpl[buf][r1w + col];
            }
            #pragma unroll
            for (int na = 0; na < 8; na++)
                mma_bf16_16x8x16(o[na][0], o[na][1], o[na][2], o[na][3],
                                 ph[0], ph[1], ph[2], ph[3], vb[na][0], vb[na][1]);
        }
        buf ^= 1;
    }

    const float inv0 = 1.f / l0, inv1 = 1.f / l1;
    const long ob0 = (long)(b * SEQ + row0) * EMB + hoff;
    const long ob1 = ob0 + 8L * EMB;
    #pragma unroll
    for (int na = 0; na < 8; na++) {
        int col = na * 8 + 2 * t;
        float2 w0 = make_float2(o[na][0] * inv0, o[na][1] * inv0);
        float2 w1 = make_float2(o[na][2] * inv1, o[na][3] * inv1);
        *reinterpret_cast<float2*>(g_attn + ob0 + col) = w0;
        *reinterpret_cast<float2*>(g_attn + ob1 + col) = w1;
    }
}

// ---------------------------------------------------------------------------
// Launch: five kernel launches, nothing else.
// ---------------------------------------------------------------------------
extern "C" void kernel_launch(void* const* d_in, const int* in_sizes, int n_in,
                              void* d_out, int out_size)
{
    const float* hidden = (const float*)d_in[0];
    const float* w_attn = (const float*)d_in[1];
    const float* b_attn = (const float*)d_in[2];
    const float* w_proj = (const float*)d_in[3];
    const float* b_proj = (const float*)d_in[4];
    float* out = (float*)d_out;

    // 1) QKV projection (tf32 TC) -> g_qkv
    qkv_tf32_kernel<<<dim3(QKV_N / 128, ROWS / 128), 256>>>(hidden, w_attn, b_attn);

    // 2) Presplit K/V into bf16 hi/lo packed word layout
    presplit_k_kernel<<<ROWS, 256>>>();
    presplit_v_kernel<<<ROWS / 2, 256>>>();

    // 3) Causal MHA flash attention (32-key tiles, cp.async, occ 2) -> g_attn
    flash_attn_mma_kernel<<<dim3(SEQ / 128, HEADS, BATCH), 256>>>();

    // 4) Output projection (tf32 TC) -> out
    proj_tf32_kernel<<<dim3(EMB / 128, ROWS / 128), 256>>>(w_proj, b_proj, out);
}